// round 4
// baseline (speedup 1.0000x reference)
#include <cuda_runtime.h>

// ---------------------------------------------------------------------------
// Attention_90898687852593: fused attention block, fp32 SIMT baseline.
//   B=2048, D=1024, H=8, DH=64, INNER=512.  Attention is over the flattened
//   (B*H)=16384 axis with head dim 64 (reshape of row-major buffers is a
//   pure reinterpret).
// Pipeline:
//   Q = x@Wq            [2048,512]  -> view [16384,64]
//   K = x@Wkv[:, :512]  [2048,512]  -> view [16384,64]
//   V = x@Wkv[:, 512:]  [2048,512]  -> view [16384,64]
//   Ao = flash_softmax(Q Kt * 0.125) V   [16384,64] -> view [2048,512]
//   out = Ao@Wout + bout  [2048,1024]
// ---------------------------------------------------------------------------

#define NROWS 16384   // B*H
#define DHEAD 64

static __device__ float g_Q[2048 * 512];
static __device__ float g_K[2048 * 512];
static __device__ float g_V[2048 * 512];
static __device__ float g_Ao[2048 * 512];

// ---------------------------------------------------------------------------
// Generic 64x64 tiled fp32 GEMM: C[M,N] = A[M,K]@B[K,N] (+ bias), all dims
// multiples of 64 (K multiple of 16). 256 threads, 4x4 register microtile.
// ---------------------------------------------------------------------------
__global__ __launch_bounds__(256, 2)
void gemm64(const float* __restrict__ A, int lda,
            const float* __restrict__ B, int ldb,
            float* __restrict__ C, int ldc,
            int Kdim, const float* __restrict__ bias)
{
    __shared__ float As[16 * 64];   // As[k][m] (transposed)
    __shared__ float Bs[16 * 64];   // Bs[k][n]

    const int t  = threadIdx.x;
    const int tx = t & 15;
    const int ty = t >> 4;
    const int m0 = blockIdx.y * 64;
    const int n0 = blockIdx.x * 64;

    const int arow = t >> 2;            // 0..63
    const int akq  = (t & 3) << 2;      // 0,4,8,12
    const int brow = t >> 4;            // 0..15
    const int bnq  = (t & 15) << 2;     // 0..60

    float acc[4][4] = {};

    for (int k0 = 0; k0 < Kdim; k0 += 16) {
        float4 av = *(const float4*)(A + (size_t)(m0 + arow) * lda + k0 + akq);
        float4 bv = *(const float4*)(B + (size_t)(k0 + brow) * ldb + n0 + bnq);
        As[(akq + 0) * 64 + arow] = av.x;
        As[(akq + 1) * 64 + arow] = av.y;
        As[(akq + 2) * 64 + arow] = av.z;
        As[(akq + 3) * 64 + arow] = av.w;
        *(float4*)(Bs + brow * 64 + bnq) = bv;
        __syncthreads();

        #pragma unroll
        for (int kk = 0; kk < 16; kk++) {
            float4 a4 = *(const float4*)(As + kk * 64 + 4 * ty);
            float4 b4 = *(const float4*)(Bs + kk * 64 + 4 * tx);
            float ar[4] = {a4.x, a4.y, a4.z, a4.w};
            float br[4] = {b4.x, b4.y, b4.z, b4.w};
            #pragma unroll
            for (int i = 0; i < 4; i++)
                #pragma unroll
                for (int j = 0; j < 4; j++)
                    acc[i][j] += ar[i] * br[j];
        }
        __syncthreads();
    }

    float4 bv = make_float4(0.f, 0.f, 0.f, 0.f);
    if (bias) bv = *(const float4*)(bias + n0 + 4 * tx);
    #pragma unroll
    for (int i = 0; i < 4; i++) {
        float4 o;
        o.x = acc[i][0] + bv.x;
        o.y = acc[i][1] + bv.y;
        o.z = acc[i][2] + bv.z;
        o.w = acc[i][3] + bv.w;
        *(float4*)(C + (size_t)(m0 + 4 * ty + i) * ldc + n0 + 4 * tx) = o;
    }
}

// ---------------------------------------------------------------------------
// Flash attention, fp32. One CTA per 64 query rows, stream over all 16384
// keys in tiles of 64. Online softmax (running max/sum), P staged via SMEM
// for the PV GEMM. 256 threads = 16x16, 4x4 microtiles.
// ---------------------------------------------------------------------------
__global__ __launch_bounds__(256, 3)
void flash64(const float* __restrict__ Q, const float* __restrict__ K,
             const float* __restrict__ V, float* __restrict__ O)
{
    extern __shared__ float sm[];
    float* Qs = sm;             // [64][64]  Qs[d][m]  (transposed)
    float* Ks = sm + 4096;      // [64][64]  Ks[d][n]  (transposed)
    float* Vs = sm + 8192;      // [64][64]  Vs[n][d]
    float* Ps = sm + 12288;     // [64][65]  Ps[m][n]  (padded)
    const int PSS = 65;

    const int t  = threadIdx.x;
    const int tx = t & 15;
    const int ty = t >> 4;
    const int r0 = blockIdx.x * 64;
    const float scale = 0.125f;   // DH^-0.5

    // Load the Q tile once (transposed).
    #pragma unroll
    for (int i = 0; i < 4; i++) {
        int idx = t + 256 * i;          // 0..1023 float4s
        int row = idx >> 4;             // 0..63
        int c4  = (idx & 15) << 2;      // 0..60
        float4 qv = *(const float4*)(Q + (size_t)(r0 + row) * DHEAD + c4);
        Qs[(c4 + 0) * 64 + row] = qv.x;
        Qs[(c4 + 1) * 64 + row] = qv.y;
        Qs[(c4 + 2) * 64 + row] = qv.z;
        Qs[(c4 + 3) * 64 + row] = qv.w;
    }

    float mrow[4], lrow[4];
    float acc[4][4] = {};
    #pragma unroll
    for (int a = 0; a < 4; a++) { mrow[a] = -1e30f; lrow[a] = 0.f; }

    for (int kt = 0; kt < NROWS; kt += 64) {
        __syncthreads();   // previous tile's Ks/Vs/Ps fully consumed

        // Load K tile (transposed) + V tile (direct).
        #pragma unroll
        for (int i = 0; i < 4; i++) {
            int idx = t + 256 * i;
            int row = idx >> 4;
            int c4  = (idx & 15) << 2;
            float4 kv = *(const float4*)(K + (size_t)(kt + row) * DHEAD + c4);
            Ks[(c4 + 0) * 64 + row] = kv.x;
            Ks[(c4 + 1) * 64 + row] = kv.y;
            Ks[(c4 + 2) * 64 + row] = kv.z;
            Ks[(c4 + 3) * 64 + row] = kv.w;
            float4 vv = *(const float4*)(V + (size_t)(kt + row) * DHEAD + c4);
            *(float4*)(Vs + row * 64 + c4) = vv;
        }
        __syncthreads();

        // S = Q @ K^T for this tile (4x4 per thread).
        float s[4][4] = {};
        #pragma unroll 8
        for (int kk = 0; kk < 64; kk++) {
            float4 a4 = *(const float4*)(Qs + kk * 64 + 4 * ty);
            float4 b4 = *(const float4*)(Ks + kk * 64 + 4 * tx);
            float ar[4] = {a4.x, a4.y, a4.z, a4.w};
            float br[4] = {b4.x, b4.y, b4.z, b4.w};
            #pragma unroll
            for (int i = 0; i < 4; i++)
                #pragma unroll
                for (int j = 0; j < 4; j++)
                    s[i][j] += ar[i] * br[j];
        }

        // Online softmax update.
        #pragma unroll
        for (int a = 0; a < 4; a++) {
            #pragma unroll
            for (int b = 0; b < 4; b++) s[a][b] *= scale;

            float v = fmaxf(fmaxf(s[a][0], s[a][1]), fmaxf(s[a][2], s[a][3]));
            #pragma unroll
            for (int off = 8; off >= 1; off >>= 1)
                v = fmaxf(v, __shfl_xor_sync(0xffffffffu, v, off));

            float nm = fmaxf(mrow[a], v);
            float al = __expf(mrow[a] - nm);
            mrow[a] = nm;

            float sum = 0.f;
            #pragma unroll
            for (int b = 0; b < 4; b++) {
                s[a][b] = __expf(s[a][b] - nm);
                sum += s[a][b];
            }
            #pragma unroll
            for (int off = 8; off >= 1; off >>= 1)
                sum += __shfl_xor_sync(0xffffffffu, sum, off);

            lrow[a] = lrow[a] * al + sum;
            #pragma unroll
            for (int b = 0; b < 4; b++) acc[a][b] *= al;
        }

        // Stage P in SMEM for the PV GEMM.
        #pragma unroll
        for (int a = 0; a < 4; a++)
            #pragma unroll
            for (int b = 0; b < 4; b++)
                Ps[(4 * ty + a) * PSS + 4 * tx + b] = s[a][b];
        __syncthreads();

        // O += P @ V
        #pragma unroll 8
        for (int kk = 0; kk < 64; kk++) {
            float4 v4 = *(const float4*)(Vs + kk * 64 + 4 * tx);
            float vr[4] = {v4.x, v4.y, v4.z, v4.w};
            float pr[4];
            #pragma unroll
            for (int a = 0; a < 4; a++) pr[a] = Ps[(4 * ty + a) * PSS + kk];
            #pragma unroll
            for (int a = 0; a < 4; a++)
                #pragma unroll
                for (int b = 0; b < 4; b++)
                    acc[a][b] += pr[a] * vr[b];
        }
    }

    // Normalize + write out.
    #pragma unroll
    for (int a = 0; a < 4; a++) {
        float rl = 1.f / lrow[a];
        float4 o;
        o.x = acc[a][0] * rl;
        o.y = acc[a][1] * rl;
        o.z = acc[a][2] * rl;
        o.w = acc[a][3] * rl;
        *(float4*)(O + (size_t)(r0 + 4 * ty + a) * DHEAD + 4 * tx) = o;
    }
}

// ---------------------------------------------------------------------------
extern "C" void kernel_launch(void* const* d_in, const int* in_sizes, int n_in,
                              void* d_out, int out_size)
{
    (void)in_sizes; (void)n_in; (void)out_size;
    const float* x    = (const float*)d_in[0];   // [2048,1024]
    const float* Wq   = (const float*)d_in[1];   // [1024,512]
    const float* Wkv  = (const float*)d_in[2];   // [1024,1024]
    const float* Wout = (const float*)d_in[3];   // [512,1024]
    const float* bout = (const float*)d_in[4];   // [1024]
    float* out = (float*)d_out;                  // [2048,1024]

    float *Q, *K, *V, *Ao;
    cudaGetSymbolAddress((void**)&Q,  g_Q);
    cudaGetSymbolAddress((void**)&K,  g_K);
    cudaGetSymbolAddress((void**)&V,  g_V);
    cudaGetSymbolAddress((void**)&Ao, g_Ao);

    // Projections.
    gemm64<<<dim3(512 / 64, 2048 / 64), 256>>>(x, 1024, Wq, 512, Q, 512, 1024, nullptr);
    gemm64<<<dim3(512 / 64, 2048 / 64), 256>>>(x, 1024, Wkv, 1024, K, 512, 1024, nullptr);
    gemm64<<<dim3(512 / 64, 2048 / 64), 256>>>(x, 1024, Wkv + 512, 1024, V, 512, 1024, nullptr);

    // Flash attention over the flattened 16384x64 view.
    const int smem = (4096 * 3 + 64 * 65) * (int)sizeof(float);  // 65792 B
    cudaFuncSetAttribute(flash64, cudaFuncAttributeMaxDynamicSharedMemorySize, smem);
    flash64<<<NROWS / 64, 256, smem>>>(Q, K, V, Ao);

    // Output projection + bias.
    gemm64<<<dim3(1024 / 64, 2048 / 64), 256>>>(Ao, 512, Wout, 1024, out, 1024, 512, bout);
}